// round 10
// baseline (speedup 1.0000x reference)
#include <cuda_runtime.h>
#include <cuda_bf16.h>
#include <cstdint>

// B=1024, T=1024, D=2, H=32, L=3.
// Algebra: only x[b,T-1,:] matters; hx==0 -> Wh dead, biases fold;
// cx==0 in layer 0 -> its forget gate dead.
//
// Changes vs R5 best (evidence: all pipes idle, approaching launch/clock
// floor; critical path = LDG(L2)->STS->bar->LDS/FMA/MUFU chain):
//  * biases b1/b2 loaded per-lane directly from L2 (coalesced) -> no smem
//    bias staging, latency hidden under W1/W2 wait
//  * activations via inline-PTX ex2.approx + rcp.approx: guaranteed
//    single-MUFU codegen independent of harness compile flags
//  * __launch_bounds__(256,1)

#define BB 1024
#define TT 1024
#define DD 2
#define HH 32
#define GG 128           // 4*H
#define WPAD 36          // row pitch in floats: 16B multiple, bank-spreading
#define THREADS 256
#define WARPS 8
#define NBLOCKS (BB / WARPS)   // 128

#define NLOG2E -1.4426950408889634f   // -log2(e)
#define LOG2E2  2.8853900817779268f   //  2*log2(e)

__device__ __forceinline__ float ex2_approx(float v) {
    float r;
    asm("ex2.approx.ftz.f32 %0, %1;" : "=f"(r) : "f"(v));
    return r;
}
__device__ __forceinline__ float rcp_approx(float v) {
    float r;
    asm("rcp.approx.ftz.f32 %0, %1;" : "=f"(r) : "f"(v));
    return r;
}

// sigmoid(v) = 1 / (1 + e^-v)
__device__ __forceinline__ float fast_sigmoid(float v) {
    return rcp_approx(1.0f + ex2_approx(NLOG2E * v));
}
// tanh(v) = 1 - 2 / (1 + e^{2v})
__device__ __forceinline__ float fast_tanh(float v) {
    return fmaf(-2.0f, rcp_approx(1.0f + ex2_approx(LOG2E2 * v)), 1.0f);
}

__global__ __launch_bounds__(THREADS, 1)
void lstm_last_step_kernel(
    const float* __restrict__ x,
    const float* __restrict__ Wx0, const float* __restrict__ bx0, const float* __restrict__ bh0,
    const float* __restrict__ Wx1, const float* __restrict__ bx1, const float* __restrict__ bh1,
    const float* __restrict__ Wx2, const float* __restrict__ bx2, const float* __restrict__ bh2,
    const float* __restrict__ Wfc, const float* __restrict__ bfc,
    float* __restrict__ out)
{
    __shared__ float sW1[GG * WPAD];      // [128][36] padded row-major, 18 KB
    __shared__ float sW2[GG * WPAD];      // 18 KB

    const int tid  = threadIdx.x;
    const int warp = tid >> 5;
    const int lane = tid & 31;
    const int b = blockIdx.x * WARPS + warp;   // one warp per batch row

    const int kI = lane;
    const int kF = 32 + lane;
    const int kG = 64 + lane;
    const int kO = 96 + lane;

    // ---- issue W1/W2 staging loads first (float4, fully coalesced) ----
    const float4* W1v = (const float4*)Wx1;   // 1024 float4 total
    const float4* W2v = (const float4*)Wx2;
    float4 r1[4], r2[4];
    #pragma unroll
    for (int j = 0; j < 4; j++) {
        r1[j] = W1v[tid + 256 * j];
        r2[j] = W2v[tid + 256 * j];
    }

    // ---- everything else straight from L2, per-lane (latency hidden) ----
    const float2 xv = *(const float2*)(x + (size_t)b * TT * DD + (size_t)(TT - 1) * DD);
    const float2* W0v = (const float2*)Wx0;            // row k -> one float2
    const float2 wI0 = W0v[kI];
    const float2 wG0 = W0v[kG];
    const float2 wO0 = W0v[kO];
    const float b0I = bx0[kI] + bh0[kI];
    const float b0G = bx0[kG] + bh0[kG];
    const float b0O = bx0[kO] + bh0[kO];
    const float b1I = bx1[kI] + bh1[kI];
    const float b1F = bx1[kF] + bh1[kF];
    const float b1G = bx1[kG] + bh1[kG];
    const float b1O = bx1[kO] + bh1[kO];
    const float b2I = bx2[kI] + bh2[kI];
    const float b2F = bx2[kF] + bh2[kF];
    const float b2G = bx2[kG] + bh2[kG];
    const float b2O = bx2[kO] + bh2[kO];
    const float wfc  = Wfc[lane];
    const float bfcv = bfc[0];

    // ---- store staged W1/W2 into padded smem ----
    #pragma unroll
    for (int j = 0; j < 4; j++) {
        const int i = tid + 256 * j;       // float4 index 0..1023
        const int k = i >> 3;              // gate row 0..127 (8 float4/row)
        const int q = i & 7;               // float4 within row
        ((float4*)(sW1 + k * WPAD))[q] = r1[j];
        ((float4*)(sW2 + k * WPAD))[q] = r2[j];
    }

    // ---- layer 0 (cx = 0 -> forget gate dead), overlaps staging ----
    float gI = fmaf(wI0.x, xv.x, fmaf(wI0.y, xv.y, b0I));
    float gG = fmaf(wG0.x, xv.x, fmaf(wG0.y, xv.y, b0G));
    float gO = fmaf(wO0.x, xv.x, fmaf(wO0.y, xv.y, b0O));

    float c = fast_sigmoid(gI) * fast_tanh(gG);
    float h = fast_sigmoid(gO) * fast_tanh(c);

    __syncthreads();

    // ---- layer 1: gates = W1 @ h + b1, h broadcast via shfl ----
    {
        const float4* rI = (const float4*)(sW1 + kI * WPAD);
        const float4* rF = (const float4*)(sW1 + kF * WPAD);
        const float4* rG = (const float4*)(sW1 + kG * WPAD);
        const float4* rO = (const float4*)(sW1 + kO * WPAD);

        float aI = b1I, aF = b1F, aG = b1G, aO = b1O;
        #pragma unroll
        for (int q = 0; q < HH / 4; q++) {
            const float h0 = __shfl_sync(0xffffffffu, h, 4 * q + 0);
            const float h1 = __shfl_sync(0xffffffffu, h, 4 * q + 1);
            const float h2 = __shfl_sync(0xffffffffu, h, 4 * q + 2);
            const float h3 = __shfl_sync(0xffffffffu, h, 4 * q + 3);
            const float4 wI = rI[q];
            const float4 wF = rF[q];
            const float4 wG = rG[q];
            const float4 wO = rO[q];
            aI = fmaf(wI.x, h0, fmaf(wI.y, h1, fmaf(wI.z, h2, fmaf(wI.w, h3, aI))));
            aF = fmaf(wF.x, h0, fmaf(wF.y, h1, fmaf(wF.z, h2, fmaf(wF.w, h3, aF))));
            aG = fmaf(wG.x, h0, fmaf(wG.y, h1, fmaf(wG.z, h2, fmaf(wG.w, h3, aG))));
            aO = fmaf(wO.x, h0, fmaf(wO.y, h1, fmaf(wO.z, h2, fmaf(wO.w, h3, aO))));
        }
        c = fmaf(c, fast_sigmoid(aF), fast_sigmoid(aI) * fast_tanh(aG));
        h = fast_sigmoid(aO) * fast_tanh(c);
    }

    // ---- layer 2 ----
    {
        const float4* rI = (const float4*)(sW2 + kI * WPAD);
        const float4* rF = (const float4*)(sW2 + kF * WPAD);
        const float4* rG = (const float4*)(sW2 + kG * WPAD);
        const float4* rO = (const float4*)(sW2 + kO * WPAD);

        float aI = b2I, aF = b2F, aG = b2G, aO = b2O;
        #pragma unroll
        for (int q = 0; q < HH / 4; q++) {
            const float h0 = __shfl_sync(0xffffffffu, h, 4 * q + 0);
            const float h1 = __shfl_sync(0xffffffffu, h, 4 * q + 1);
            const float h2 = __shfl_sync(0xffffffffu, h, 4 * q + 2);
            const float h3 = __shfl_sync(0xffffffffu, h, 4 * q + 3);
            const float4 wI = rI[q];
            const float4 wF = rF[q];
            const float4 wG = rG[q];
            const float4 wO = rO[q];
            aI = fmaf(wI.x, h0, fmaf(wI.y, h1, fmaf(wI.z, h2, fmaf(wI.w, h3, aI))));
            aF = fmaf(wF.x, h0, fmaf(wF.y, h1, fmaf(wF.z, h2, fmaf(wF.w, h3, aF))));
            aG = fmaf(wG.x, h0, fmaf(wG.y, h1, fmaf(wG.z, h2, fmaf(wG.w, h3, aG))));
            aO = fmaf(wO.x, h0, fmaf(wO.y, h1, fmaf(wO.z, h2, fmaf(wO.w, h3, aO))));
        }
        c = fmaf(c, fast_sigmoid(aF), fast_sigmoid(aI) * fast_tanh(aG));
        h = fast_sigmoid(aO) * fast_tanh(c);
    }

    // ---- fc: out[b] = sum_j h[j] * Wfc[j] + bfc ----
    float p = h * wfc;
    #pragma unroll
    for (int off = 16; off; off >>= 1)
        p += __shfl_xor_sync(0xffffffffu, p, off);

    if (lane == 0) out[b] = p + bfcv;
}

extern "C" void kernel_launch(void* const* d_in, const int* in_sizes, int n_in,
                              void* d_out, int out_size) {
    // 0:x 1:Wx0 2:bx0 3:Wh0 4:bh0 5:Wx1 6:bx1 7:Wh1 8:bh1
    // 9:Wx2 10:bx2 11:Wh2 12:bh2 13:Wfc 14:bfc
    const float* x   = (const float*)d_in[0];
    const float* Wx0 = (const float*)d_in[1];
    const float* bx0 = (const float*)d_in[2];
    const float* bh0 = (const float*)d_in[4];
    const float* Wx1 = (const float*)d_in[5];
    const float* bx1 = (const float*)d_in[6];
    const float* bh1 = (const float*)d_in[8];
    const float* Wx2 = (const float*)d_in[9];
    const float* bx2 = (const float*)d_in[10];
    const float* bh2 = (const float*)d_in[12];
    const float* Wfc = (const float*)d_in[13];
    const float* bfc = (const float*)d_in[14];
    float* out = (float*)d_out;

    lstm_last_step_kernel<<<NBLOCKS, THREADS>>>(
        x, Wx0, bx0, bh0, Wx1, bx1, bh1, Wx2, bx2, bh2, Wfc, bfc, out);
}